// round 1
// baseline (speedup 1.0000x reference)
#include <cuda_runtime.h>
#include <cuda_bf16.h>

#define LSEQ 4608
#define CDIM 640
#define DI   1280
#define DXZ  2560
#define NPROJ 56
#define RANK  40
#define PLANE 2304          // 48*48
#define XFSZ  (640*2304)    // elements in xf output

// ---------------- scratch (static device allocations; no cudaMalloc) ----------------
__device__ float g_xn  [LSEQ*CDIM];   // layernorm output
__device__ float g_xz  [LSEQ*DXZ];    // xn @ W_in  (xp | z)
__device__ float g_xa  [LSEQ*DI];     // silu(conv(xp))
__device__ float g_proj[LSEQ*NPROJ];  // xa @ W_xproj  (dtin | B | C)
__device__ float g_dt  [LSEQ*DI];     // softplus(proj[:, :40] @ W_dt + bias)
__device__ float g_yo  [LSEQ*DI];     // gated ssm output

// ---------------- helpers ----------------
__device__ __forceinline__ float silu_f(float v){
    return v / (1.0f + __expf(-v));
}

// ---------------- 1) gather + layernorm ----------------
// seq[l, c] with l = h*96 + w2 ; w2<48 -> x[c,h,w2] else y[c,h,w2-48]
__global__ void ln_kernel(const float* __restrict__ x, const float* __restrict__ yy,
                          const float* __restrict__ g, const float* __restrict__ b){
    int l  = blockIdx.x;
    int h  = l / 96;
    int w2 = l - h * 96;
    const float* src = (w2 < 48) ? (x + h*48 + w2) : (yy + h*48 + (w2-48));
    int t = threadIdx.x;   // 256 threads

    float v0 = src[(size_t)t       * PLANE];
    float v1 = src[(size_t)(t+256) * PLANE];
    float v2 = (t < 128) ? src[(size_t)(t+512) * PLANE] : 0.f;

    float s  = v0 + v1 + v2;
    float s2 = v0*v0 + v1*v1 + v2*v2;
    #pragma unroll
    for (int o = 16; o > 0; o >>= 1){
        s  += __shfl_xor_sync(0xffffffffu, s , o);
        s2 += __shfl_xor_sync(0xffffffffu, s2, o);
    }
    __shared__ float rs[8], rs2[8];
    int wid = t >> 5, lid = t & 31;
    if (lid == 0){ rs[wid] = s; rs2[wid] = s2; }
    __syncthreads();
    if (t == 0){
        float a = 0.f, a2 = 0.f;
        #pragma unroll
        for (int i = 0; i < 8; i++){ a += rs[i]; a2 += rs2[i]; }
        rs[0] = a; rs2[0] = a2;
    }
    __syncthreads();
    float mean = rs[0]  * (1.f/640.f);
    float var  = rs2[0] * (1.f/640.f) - mean*mean;
    float inv  = rsqrtf(var + 1e-5f);

    float* dst = g_xn + (size_t)l * CDIM;
    dst[t]       = (v0 - mean) * inv * g[t]       + b[t];
    dst[t + 256] = (v1 - mean) * inv * g[t + 256] + b[t + 256];
    if (t < 128)
        dst[t + 512] = (v2 - mean) * inv * g[t + 512] + b[t + 512];
}

// ---------------- 2/7) 128x128x8 register-blocked SGEMM ----------------
// MODE 0: C[row*N + col] = acc                      (GEMM1: xn @ W_in -> xz)
// MODE 1: out scatter + residual                    (GEMM2: yo @ W_out + seq -> d_out)
template<int MODE>
__global__ void sgemm128(const float* __restrict__ A, const float* __restrict__ B,
                         float* __restrict__ C, int K, int lda, int ldb, int N,
                         const float* __restrict__ rx, const float* __restrict__ ry,
                         float* __restrict__ outp){
    __shared__ float As[8][128];
    __shared__ float Bs[8][128];
    int tid = threadIdx.x;
    int bx = blockIdx.x, by = blockIdx.y;

    int arow = tid >> 1;
    int acol = (tid & 1) * 4;
    int brow = tid >> 5;
    int bcol = (tid & 31) * 4;

    const float* Ap = A + (size_t)(by*128 + arow) * lda + acol;
    const float* Bp = B + (size_t)brow * ldb + bx*128 + bcol;

    float acc[8][8];
    #pragma unroll
    for (int i = 0; i < 8; i++)
        #pragma unroll
        for (int j = 0; j < 8; j++) acc[i][j] = 0.f;

    int ty = tid >> 4, tx = tid & 15;

    for (int k0 = 0; k0 < K; k0 += 8){
        float4 av = *(const float4*)Ap;
        float4 bv = *(const float4*)Bp;
        __syncthreads();
        As[acol+0][arow] = av.x;
        As[acol+1][arow] = av.y;
        As[acol+2][arow] = av.z;
        As[acol+3][arow] = av.w;
        *(float4*)(&Bs[brow][bcol]) = bv;
        __syncthreads();
        #pragma unroll
        for (int k = 0; k < 8; k++){
            float4 a0 = *(const float4*)(&As[k][ty*8]);
            float4 a1 = *(const float4*)(&As[k][ty*8+4]);
            float4 b0 = *(const float4*)(&Bs[k][tx*8]);
            float4 b1 = *(const float4*)(&Bs[k][tx*8+4]);
            float ar[8] = {a0.x,a0.y,a0.z,a0.w,a1.x,a1.y,a1.z,a1.w};
            float br[8] = {b0.x,b0.y,b0.z,b0.w,b1.x,b1.y,b1.z,b1.w};
            #pragma unroll
            for (int i = 0; i < 8; i++)
                #pragma unroll
                for (int j = 0; j < 8; j++)
                    acc[i][j] = fmaf(ar[i], br[j], acc[i][j]);
        }
        Ap += 8;
        Bp += (size_t)8 * ldb;
    }

    if (MODE == 0){
        #pragma unroll
        for (int i = 0; i < 8; i++){
            float* crow = C + (size_t)(by*128 + ty*8 + i) * N + bx*128 + tx*8;
            float4 c0 = {acc[i][0], acc[i][1], acc[i][2], acc[i][3]};
            float4 c1 = {acc[i][4], acc[i][5], acc[i][6], acc[i][7]};
            *(float4*)(crow)     = c0;
            *(float4*)(crow + 4) = c1;
        }
    } else {
        #pragma unroll
        for (int i = 0; i < 8; i++){
            int row = by*128 + ty*8 + i;        // l
            int h   = row / 96;
            int w2  = row - h*96;
            bool isx = (w2 < 48);
            int  w   = isx ? w2 : (w2 - 48);
            const float* rsrc = (isx ? rx : ry) + h*48 + w;
            float* od = outp + (isx ? 0 : XFSZ) + h*48 + w;
            #pragma unroll
            for (int j = 0; j < 8; j++){
                int col = bx*128 + tx*8 + j;    // c
                od[(size_t)col * PLANE] = acc[i][j] + rsrc[(size_t)col * PLANE];
            }
        }
    }
}

// ---------------- 3) causal depthwise conv (K=4) + SiLU ----------------
__global__ void conv_silu_kernel(const float* __restrict__ cw){
    int d = blockIdx.x * 256 + threadIdx.x;   // 0..1279 (grid.x = 5)
    int l = blockIdx.y;                       // 0..4607
    float4 wv = ((const float4*)cw)[d];       // conv_w[d, 0, 0..3]
    const float* xp = g_xz + d;               // xp = xz[:, :1280]
    float acc = wv.w * xp[(size_t)l * DXZ];
    if (l >= 1) acc += wv.z * xp[(size_t)(l-1) * DXZ];
    if (l >= 2) acc += wv.y * xp[(size_t)(l-2) * DXZ];
    if (l >= 3) acc += wv.x * xp[(size_t)(l-3) * DXZ];
    g_xa[(size_t)l * DI + d] = silu_f(acc);
}

// ---------------- 4) proj GEMM: xa(4608x1280) @ W_xproj(1280x56) ----------------
// 64x64(=56) tile, BK=16, 4x4 thread tiles
__global__ void proj_gemm(const float* __restrict__ A, const float* __restrict__ B,
                          float* __restrict__ C){
    __shared__ float As[16][64];
    __shared__ float Bs[16][64];
    int tid = threadIdx.x;
    int by  = blockIdx.x;                 // 0..71

    int arow = tid >> 2;                  // 0..63
    int acol = (tid & 3) * 4;             // 0,4,8,12
    const float* Ap = A + (size_t)(by*64 + arow) * DI + acol;

    float acc[4][4];
    #pragma unroll
    for (int i = 0; i < 4; i++)
        #pragma unroll
        for (int j = 0; j < 4; j++) acc[i][j] = 0.f;

    int ty = tid >> 4, tx = tid & 15;

    for (int k0 = 0; k0 < DI; k0 += 16){
        float4 av = *(const float4*)Ap;
        float bl[4];
        #pragma unroll
        for (int q = 0; q < 4; q++){
            int e = tid*4 + q;
            int r = e >> 6, c = e & 63;
            bl[q] = (c < NPROJ) ? B[(size_t)(k0 + r) * NPROJ + c] : 0.f;
        }
        __syncthreads();
        As[acol+0][arow] = av.x;
        As[acol+1][arow] = av.y;
        As[acol+2][arow] = av.z;
        As[acol+3][arow] = av.w;
        #pragma unroll
        for (int q = 0; q < 4; q++){
            int e = tid*4 + q;
            Bs[e >> 6][e & 63] = bl[q];
        }
        __syncthreads();
        #pragma unroll
        for (int k = 0; k < 16; k++){
            float ar[4], br[4];
            #pragma unroll
            for (int i = 0; i < 4; i++) ar[i] = As[k][ty*4 + i];
            #pragma unroll
            for (int j = 0; j < 4; j++) br[j] = Bs[k][tx*4 + j];
            #pragma unroll
            for (int i = 0; i < 4; i++)
                #pragma unroll
                for (int j = 0; j < 4; j++)
                    acc[i][j] = fmaf(ar[i], br[j], acc[i][j]);
        }
        __syncthreads();
        Ap += 16;
    }
    #pragma unroll
    for (int i = 0; i < 4; i++){
        int row = by*64 + ty*4 + i;
        #pragma unroll
        for (int j = 0; j < 4; j++){
            int col = tx*4 + j;
            if (col < NPROJ) C[(size_t)row * NPROJ + col] = acc[i][j];
        }
    }
}

// ---------------- 5) dt = softplus(proj[:, :40] @ W_dt + bias), 8 rows/block ----------------
__global__ void dt_kernel(const float* __restrict__ Wdt, const float* __restrict__ bias){
    __shared__ float pr[8][RANK];
    int t  = threadIdx.x;
    int d  = blockIdx.x * 256 + t;       // grid.x = 5
    int l0 = blockIdx.y * 8;             // grid.y = 576
    if (t < 8 * RANK)
        pr[t / RANK][t % RANK] = g_proj[(size_t)(l0 + t / RANK) * NPROJ + (t % RANK)];
    __syncthreads();

    float acc[8];
    #pragma unroll
    for (int j = 0; j < 8; j++) acc[j] = 0.f;
    for (int k = 0; k < RANK; k++){
        float wv = Wdt[(size_t)k * DI + d];
        #pragma unroll
        for (int j = 0; j < 8; j++) acc[j] = fmaf(pr[j][k], wv, acc[j]);
    }
    float bb = bias[d];
    #pragma unroll
    for (int j = 0; j < 8; j++){
        float v = acc[j] + bb;
        float sp = (v > 20.f) ? v : log1pf(__expf(v));
        g_dt[(size_t)(l0 + j) * DI + d] = sp;
    }
}

// ---------------- 6) selective scan, thread per (d, s) ----------------
// h[l] = exp(dt*A_s)*h[l-1] + dt*xa*B_s ;  y = sum_s h*C_s + xa*Dp ; yo = y*silu(z)
__global__ void scan_kernel(const float* __restrict__ A_log, const float* __restrict__ Dp){
    int tid = threadIdx.x;
    int s   = tid & 7;
    int d   = blockIdx.x * 32 + (tid >> 3);   // grid.x = 40

    float Acoef = -__expf(A_log[d*8 + s]);
    float Dval  = Dp[d];

    const float* dtp = g_dt + d;
    const float* xap = g_xa + d;
    const float* zp  = g_xz + DI + d;
    const float* bp  = g_proj + RANK + s;     // B at cols 40..47, C at 48..55
    float* yop = g_yo + d;

    float h = 0.f;
    for (int l = 0; l < LSEQ; l++){
        float dtv = __ldg(dtp);
        float xav = __ldg(xap);
        float Bv  = __ldg(bp);
        float Cv  = __ldg(bp + 8);
        float dA  = __expf(dtv * Acoef);
        h = fmaf(dA, h, dtv * xav * Bv);
        float yv = h * Cv;
        yv += __shfl_xor_sync(0xffffffffu, yv, 1);
        yv += __shfl_xor_sync(0xffffffffu, yv, 2);
        yv += __shfl_xor_sync(0xffffffffu, yv, 4);
        if (s == 0){
            float zv = __ldg(zp);
            yop[0] = (yv + xav * Dval) * silu_f(zv);
        }
        dtp += DI; xap += DI; bp += NPROJ; zp += DXZ; yop += DI;
    }
}

// ---------------- launch ----------------
extern "C" void kernel_launch(void* const* d_in, const int* in_sizes, int n_in,
                              void* d_out, int out_size){
    const float* x       = (const float*)d_in[0];
    const float* y       = (const float*)d_in[1];
    const float* ln_g    = (const float*)d_in[2];
    const float* ln_b    = (const float*)d_in[3];
    const float* W_in    = (const float*)d_in[4];
    const float* conv_w  = (const float*)d_in[5];
    const float* W_xproj = (const float*)d_in[6];
    const float* W_dt    = (const float*)d_in[7];
    const float* dt_bias = (const float*)d_in[8];
    const float* A_log   = (const float*)d_in[9];
    const float* Dp      = (const float*)d_in[10];
    const float* W_out   = (const float*)d_in[11];
    float* out = (float*)d_out;

    float *xn_p, *xz_p, *xa_p, *proj_p, *dt_p, *yo_p;
    cudaGetSymbolAddress((void**)&xn_p,   g_xn);
    cudaGetSymbolAddress((void**)&xz_p,   g_xz);
    cudaGetSymbolAddress((void**)&xa_p,   g_xa);
    cudaGetSymbolAddress((void**)&proj_p, g_proj);
    cudaGetSymbolAddress((void**)&dt_p,   g_dt);
    cudaGetSymbolAddress((void**)&yo_p,   g_yo);

    // 1) gather + layernorm
    ln_kernel<<<LSEQ, 256>>>(x, y, ln_g, ln_b);

    // 2) xz = xn @ W_in   (4608 x 2560 x 640)
    sgemm128<0><<<dim3(DXZ/128, LSEQ/128), 256>>>(
        xn_p, W_in, xz_p, CDIM, CDIM, DXZ, DXZ, nullptr, nullptr, nullptr);

    // 3) xa = silu(causal_dwconv(xp))
    conv_silu_kernel<<<dim3(DI/256, LSEQ), 256>>>(conv_w);

    // 4) proj = xa @ W_xproj   (4608 x 56 x 1280)
    proj_gemm<<<LSEQ/64, 256>>>(xa_p, W_xproj, proj_p);

    // 5) dt
    dt_kernel<<<dim3(DI/256, LSEQ/8), 256>>>(W_dt, dt_bias);

    // 6) scan + gating
    scan_kernel<<<DI*8/256, 256>>>(A_log, Dp);

    // 7) out = yo @ W_out + seq, scattered into (xf | yf)
    sgemm128<1><<<dim3(CDIM/128, LSEQ/128), 256>>>(
        yo_p, W_out, nullptr, DI, DI, CDIM, CDIM, x, y, out);
}